// round 16
// baseline (speedup 1.0000x reference)
#include <cuda_runtime.h>
#include <cstdint>
#include <cstddef>

#define SEQ 4096
#define DM  1024
#define NH  16
#define HD  64
#define NKEY 32
#define NNG 4094

// Scratch (device globals: allocation-free)
__device__ float g_q[SEQ * DM];
__device__ float g_k[SEQ * DM];
__device__ float g_v[SEQ * DM];
__device__ float g_qp[SEQ * DM];      // permuted+rounded A operands
__device__ float g_kp[SEQ * DM];
__device__ float g_vp[SEQ * DM];
__device__ float g_attnp[SEQ * DM];   // attention out, permuted+rounded
__device__ float g_wqp[DM * DM];      // permuted+rounded weights [kt][n][16]
__device__ float g_wkp[DM * DM];
__device__ float g_wvp[DM * DM];
__device__ float g_wop[DM * DM];
__device__ int   g_idx_is64;

#define GCH 32
__device__ float g_pm[32][GCH];
__device__ float g_ps[32][GCH];
__device__ float g_po[32][GCH][HD];

// ---------------------------------------------------------------------------
__global__ void detect_idx_kernel(const int* __restrict__ idx32) {
    g_idx_is64 = ((idx32[1] | idx32[3] | idx32[5] | idx32[7]) == 0) ? 1 : 0;
}

// ---------------------------------------------------------------------------
// Helpers
// ---------------------------------------------------------------------------
__device__ __forceinline__ uint32_t f2tf32(float x) {
    uint32_t r;
    asm("cvt.rna.tf32.f32 %0, %1;" : "=r"(r) : "f"(x));
    return r;
}
__device__ __forceinline__ float rndf(float x) { return __uint_as_float(f2tf32(x)); }

__device__ __forceinline__ uint32_t smem_u32(const void* p) {
    uint32_t a;
    asm("{ .reg .u64 t; cvta.to.shared.u64 t, %1; cvt.u32.u64 %0, t; }" : "=r"(a) : "l"(p));
    return a;
}
__device__ __forceinline__ void cp16(uint32_t dst, const void* src) {
    asm volatile("cp.async.cg.shared.global [%0], [%1], 16;" :: "r"(dst), "l"(src));
}
__device__ __forceinline__ void mma_tf32(float c[4], const uint32_t a[4], const uint32_t b[2]) {
    asm volatile(
        "mma.sync.aligned.m16n8k8.row.col.f32.tf32.tf32.f32 "
        "{%0,%1,%2,%3}, {%4,%5,%6,%7}, {%8,%9}, {%0,%1,%2,%3};"
        : "+f"(c[0]), "+f"(c[1]), "+f"(c[2]), "+f"(c[3])
        : "r"(a[0]), "r"(a[1]), "r"(a[2]), "r"(a[3]),
          "r"(b[0]), "r"(b[1]));
}
#define NBAR(id, cnt) asm volatile("bar.sync %0, %1;" :: "r"(id), "r"(cnt) : "memory")

// ---------------------------------------------------------------------------
// Fused permute+round (z=0..2: A operands; z=3..6: weights).
// ---------------------------------------------------------------------------
__global__ __launch_bounds__(256)
void perm_all_kernel(const float* __restrict__ s0, float* __restrict__ d0,
                     const float* __restrict__ s1, float* __restrict__ d1,
                     const float* __restrict__ s2, float* __restrict__ d2,
                     const float* __restrict__ w0, float* __restrict__ p0,
                     const float* __restrict__ w1, float* __restrict__ p1,
                     const float* __restrict__ w2, float* __restrict__ p2,
                     const float* __restrict__ w3, float* __restrict__ p3) {
    const int z = blockIdx.z;
    if (z < 3) {
        const float* src = (z == 0) ? s0 : (z == 1) ? s1 : s2;
        float*       dst = (z == 0) ? d0 : (z == 1) ? d1 : d2;
        const int idx = blockIdx.x * 256 + threadIdx.x;
        const int row = idx >> 6, ch = idx & 63;
        const float4* s = (const float4*)(src + (size_t)row * DM + ch * 16);
        float4 u0 = s[0], u1 = s[1], u2 = s[2], u3 = s[3];
        float vv[16] = { u0.x,u0.y,u0.z,u0.w, u1.x,u1.y,u1.z,u1.w,
                         u2.x,u2.y,u2.z,u2.w, u3.x,u3.y,u3.z,u3.w };
        const int xa = (row >> 1) & 3;
        float4* d = (float4*)(dst + (size_t)row * DM + ch * 16);
#pragma unroll
        for (int x = 0; x < 4; x++) {
            const int kq = x ^ xa;
            float4 o;
            o.x = rndf(vv[kq]); o.y = rndf(vv[kq + 4]);
            o.z = rndf(vv[kq + 8]); o.w = rndf(vv[kq + 12]);
            d[x] = o;
        }
    } else {
        if (blockIdx.x >= 256) return;
        const int zi = z - 3;
        const float* W = (zi == 0) ? w0 : (zi == 1) ? w1 : (zi == 2) ? w2 : w3;
        float*       P = (zi == 0) ? p0 : (zi == 1) ? p1 : (zi == 2) ? p2 : p3;
        const int idx = blockIdx.x * 256 + threadIdx.x;
        const int kt = idx >> 10, n = idx & 1023;
        float out[16];
#pragma unroll
        for (int k = 0; k < 16; k++)
            out[((k & 3) << 2) + (k >> 2)] = rndf(W[(size_t)(kt * 16 + k) * DM + n]);
        float4* d = (float4*)(P + (size_t)kt * (DM * 16) + (size_t)n * 16);
#pragma unroll
        for (int x = 0; x < 4; x++)
            d[x] = make_float4(out[4 * x], out[4 * x + 1], out[4 * x + 2], out[4 * x + 3]);
    }
}

// ---------------------------------------------------------------------------
// GEMM v8: 4-stage cp.async pipeline, carried-pointer staging, precomputed
// fragment offsets, independent 8-MMA batches. (round-15 version, unchanged)
// ---------------------------------------------------------------------------
#define STG 16384
#define GEMM_SMEM (4 * STG)

__global__ void __launch_bounds__(256, 2)
gemm_v8_kernel(const float* __restrict__ A0, const float* __restrict__ W0, float* __restrict__ C0,
               const float* __restrict__ A1, const float* __restrict__ W1, float* __restrict__ C1,
               const float* __restrict__ A2, const float* __restrict__ W2, float* __restrict__ C2) {
    extern __shared__ char sm[];
    const float* Ap = (blockIdx.z == 0) ? A0 : (blockIdx.z == 1) ? A1 : A2;
    const float* Wp = (blockIdx.z == 0) ? W0 : (blockIdx.z == 1) ? W1 : W2;
    float*       C  = (blockIdx.z == 0) ? C0 : (blockIdx.z == 1) ? C1 : C2;

    const uint32_t sb = smem_u32(sm);
    const int t = threadIdx.x, lane = t & 31, warp = t >> 5;
    const int wr = warp >> 2, wc = warp & 3;
    const int bm = blockIdx.y * 128, bn = blockIdx.x * 128;

    const float* qA0 = Ap + (size_t)(bm + (t >> 2)) * DM + (t & 3) * 4;
    const float* qA1 = qA0 + (size_t)64 * DM;
    const float* qB0 = Wp + (size_t)bn * 16 + t * 4;
    const float* qB1 = qB0 + 1024;
    const uint32_t dA0 = sb + t * 16, dA1 = sb + (t + 256) * 16;
    const uint32_t dB0 = sb + 8192 + t * 16, dB1 = sb + 8192 + (t + 256) * 16;

    const int g = lane & 3;
    int offA0[4], offA1[4], offB[4];
    {
        const int c0 = wc * 32 + (lane >> 2);
#pragma unroll
        for (int ni = 0; ni < 4; ni++) offB[ni] = (c0 + ni * 8) * 4 + g;
#pragma unroll
        for (int mi = 0; mi < 4; mi++) {
            const int rlo = wr * 64 + mi * 16 + (lane >> 2);
            const int rhi = rlo + 8;
            offA0[mi] = rlo * 4 + ((g ^ (rlo >> 1)) & 3);
            offA1[mi] = rhi * 4 + ((g ^ (rhi >> 1)) & 3);
        }
    }

    float acc[4][4][4];
#pragma unroll
    for (int mi = 0; mi < 4; mi++)
#pragma unroll
        for (int ni = 0; ni < 4; ni++)
#pragma unroll
            for (int e = 0; e < 4; e++) acc[mi][ni][e] = 0.f;

#pragma unroll
    for (int pt = 0; pt < 3; pt++) {
        cp16(dA0 + pt * STG, qA0 + pt * 16);
        cp16(dA1 + pt * STG, qA1 + pt * 16);
        cp16(dB0 + pt * STG, qB0 + (size_t)pt * DM * 16);
        cp16(dB1 + pt * STG, qB1 + (size_t)pt * DM * 16);
        asm volatile("cp.async.commit_group;" ::: "memory");
    }
    const float* rA0 = qA0 + 48;
    const float* rA1 = qA1 + 48;
    const float* rB0 = qB0 + (size_t)3 * DM * 16;
    const float* rB1 = qB1 + (size_t)3 * DM * 16;

    const int NT = 64;
#pragma unroll 4
    for (int kt = 0; kt < NT; kt++) {
        asm volatile("cp.async.wait_group 2;" ::: "memory");
        __syncthreads();

        const uint32_t s = kt & 3;
        const float4* as4 = (const float4*)(sm + s * STG);
        const float4* bs4 = (const float4*)(sm + s * STG + 8192);

        float4 bq[4];
#pragma unroll
        for (int ni = 0; ni < 4; ni++) bq[ni] = bs4[offB[ni]];

#pragma unroll
        for (int half = 0; half < 2; half++) {
            float4 alo[2], ahi[2];
#pragma unroll
            for (int u = 0; u < 2; u++) {
                const int mi = half * 2 + u;
                alo[u] = as4[offA0[mi]];
                ahi[u] = as4[offA1[mi]];
            }
#pragma unroll
            for (int u = 0; u < 2; u++) {
                const int mi = half * 2 + u;
                uint32_t a0[4] = { __float_as_uint(alo[u].x), __float_as_uint(ahi[u].x),
                                   __float_as_uint(alo[u].y), __float_as_uint(ahi[u].y) };
#pragma unroll
                for (int ni = 0; ni < 4; ni++) {
                    uint32_t b0[2] = { __float_as_uint(bq[ni].x), __float_as_uint(bq[ni].y) };
                    mma_tf32(acc[mi][ni], a0, b0);
                }
            }
#pragma unroll
            for (int u = 0; u < 2; u++) {
                const int mi = half * 2 + u;
                uint32_t a1[4] = { __float_as_uint(alo[u].z), __float_as_uint(ahi[u].z),
                                   __float_as_uint(alo[u].w), __float_as_uint(ahi[u].w) };
#pragma unroll
                for (int ni = 0; ni < 4; ni++) {
                    uint32_t b1[2] = { __float_as_uint(bq[ni].z), __float_as_uint(bq[ni].w) };
                    mma_tf32(acc[mi][ni], a1, b1);
                }
            }
        }

        if (kt + 3 < NT) {
            const uint32_t ns = (kt + 3) & 3;
            cp16(dA0 + ns * STG, rA0);
            cp16(dA1 + ns * STG, rA1);
            cp16(dB0 + ns * STG, rB0);
            cp16(dB1 + ns * STG, rB1);
        }
        asm volatile("cp.async.commit_group;" ::: "memory");
        rA0 += 16; rA1 += 16;
        rB0 += (size_t)DM * 16; rB1 += (size_t)DM * 16;
    }

#pragma unroll
    for (int mi = 0; mi < 4; mi++) {
#pragma unroll
        for (int ni = 0; ni < 4; ni++) {
            const int r = bm + wr * 64 + mi * 16 + (lane >> 2);
            const int c = bn + wc * 32 + ni * 8 + ((lane & 3) << 1);
            float2 v0 = make_float2(acc[mi][ni][0], acc[mi][ni][1]);
            float2 v1 = make_float2(acc[mi][ni][2], acc[mi][ni][3]);
            *(float2*)(C + (size_t)r * DM + c) = v0;
            *(float2*)(C + (size_t)(r + 8) * DM + c) = v1;
        }
    }
}

// ---------------------------------------------------------------------------
// Fused sparse + global-part attention (round-15 version, unchanged logic).
// Round-16 change is host-side: PreferredSharedMemoryCarveout = 100% so
// 4 blocks/SM fit (was carveout-capped at 2 -> occ 46%).
// ---------------------------------------------------------------------------
#define TQ 8
#define WROWS 30
#define WPAD 132

__global__ __launch_bounds__(512)
void sparse_global_kernel(const float* __restrict__ qb, const float* __restrict__ kb,
                          const float* __restrict__ vb, const void* __restrict__ idxp,
                          float* __restrict__ obp) {
    __shared__ float sQ[TQ][128];
    __shared__ float sK[WROWS][WPAD];
    __shared__ float sV[WROWS][WPAD];
    __shared__ float gq[4][HD];
    __shared__ float gle[4][128];
    __shared__ float gred[4][128];

    const int t = threadIdx.x;

    if (blockIdx.x >= 512) {
        const int sub = t >> 7;
        const int tt = t & 127;
        const int unit = ((blockIdx.x - 512) * 8 + blockIdx.y) * 4 + sub;
        const int c = unit & (GCH - 1);
        const int ph = unit >> 5;
        const int h = ph & (NH - 1);
        const int p = (ph >> 4) ? (SEQ - 1) : 0;
        const int j0 = c * 128;
        const int bid = sub + 1;

        if (tt < HD / 4)
            ((float4*)gq[sub])[tt] = *(const float4*)(qb + (size_t)p * DM + h * HD + tt * 4);
        NBAR(bid, 128);

        const float* kr = kb + (size_t)(j0 + tt) * DM + h * HD;
        float a = 0.f;
#pragma unroll
        for (int cc = 0; cc < 16; cc++) {
            float4 kv = ((const float4*)kr)[cc];
            float4 qv = ((const float4*)gq[sub])[cc];
            a += kv.x * qv.x + kv.y * qv.y + kv.z * qv.z + kv.w * qv.w;
        }
        float logit = a * 0.125f;

        gred[sub][tt] = logit; NBAR(bid, 128);
#pragma unroll
        for (int o = 64; o > 0; o >>= 1) {
            if (tt < o) gred[sub][tt] = fmaxf(gred[sub][tt], gred[sub][tt + o]);
            NBAR(bid, 128);
        }
        const float m = gred[sub][0];
        NBAR(bid, 128);

        float e = __expf(logit - m);
        gle[sub][tt] = e;
        gred[sub][tt] = e; NBAR(bid, 128);
#pragma unroll
        for (int o = 64; o > 0; o >>= 1) {
            if (tt < o) gred[sub][tt] += gred[sub][tt + o];
            NBAR(bid, 128);
        }
        const float s = gred[sub][0];
        NBAR(bid, 128);

        const int d = tt & (HD - 1);
        const int hh = tt >> 6;
        float o = 0.f;
#pragma unroll 4
        for (int j = hh * 64; j < hh * 64 + 64; j++)
            o += gle[sub][j] * vb[(size_t)(j0 + j) * DM + h * HD + d];
        gred[sub][tt] = o; NBAR(bid, 128);
        if (tt < HD)
            g_po[ph][c][tt] = gred[sub][tt] + gred[sub][tt + 64];
        if (tt == 0) { g_pm[ph][c] = m; g_ps[ph][c] = s; }
        return;
    }

    const int pbase = blockIdx.x * TQ + 1;
    const int hb = blockIdx.y * 128;
    const int r0 = pbase - 11;

    if (t < 256) {
        int row = t >> 5, i = (t & 31) << 2;
        int p = pbase + row;
        if (p <= SEQ - 2)
            *(float4*)&sQ[row][i] = *(const float4*)(qb + (size_t)p * DM + hb + i);
    }
#pragma unroll
    for (int f = 0; f < 2 * WROWS * 32; f += 512) {
        int gg = f + t;
        if (gg < 2 * WROWS * 32) {
            int sel = (gg >= WROWS * 32);
            int rem = sel ? gg - WROWS * 32 : gg;
            int row = rem >> 5, i = (rem & 31) << 2;
            int rg = r0 + row;
            rg = rg < 0 ? 0 : (rg > SEQ - 1 ? SEQ - 1 : rg);
            const float* src = (sel ? vb : kb) + (size_t)rg * DM + hb + i;
            float* dst = (sel ? &sV[0][0] : &sK[0][0]) + row * WPAD + i;
            *(float4*)dst = *(const float4*)src;
        }
    }
    __syncthreads();

    const int warp = t >> 5, lane = t & 31;
    const int ql = warp & 7, hl = warp >> 3;
    const int p = pbase + ql;
    if (p > SEQ - 2) return;
    const int n = p - 1;
    const int hdim = hb + hl * 64;

    const float4* qp4 = (const float4*)&sQ[ql][hl * 64];

    int row = 0;
    float logit;
    if (lane >= 9) {
        const float4* kp4 = (const float4*)&sK[ql + lane - 9][hl * 64];
        float a = 0.f;
#pragma unroll
        for (int c = 0; c < 16; c++) {
            float4 kv = kp4[c];
            float4 qv = qp4[c];
            a += kv.x * qv.x + kv.y * qv.y + kv.z * qv.z + kv.w * qv.w;
        }
        logit = a * 0.125f;
    } else {
        if (lane >= 1) {
            row = g_idx_is64
                ? (int)((const long long*)idxp)[(size_t)n * NKEY + lane]
                : ((const int*)idxp)[(size_t)n * NKEY + lane];
        }
        const float4* kp4 = (const float4*)(kb + (size_t)row * DM + hdim);
        float a = 0.f;
#pragma unroll
        for (int c = 0; c < 16; c++) {
            float4 kv = kp4[c];
            float4 qv = qp4[c];
            a += kv.x * qv.x + kv.y * qv.y + kv.z * qv.z + kv.w * qv.w;
        }
        logit = a * 0.125f;
    }

    float m = logit;
#pragma unroll
    for (int o = 16; o > 0; o >>= 1) m = fmaxf(m, __shfl_xor_sync(0xFFFFFFFFu, m, o));
    float e = __expf(logit - m);
    float s = e;
#pragma unroll
    for (int o = 16; o > 0; o >>= 1) s += __shfl_xor_sync(0xFFFFFFFFu, s, o);
    const float prob = e / s;

    float o0 = 0.f, o1 = 0.f;
#pragma unroll
    for (int j = 9; j < 32; j++) {
        float pj = __shfl_sync(0xFFFFFFFFu, prob, j);
        float2 vv = *(const float2*)&sV[ql + j - 9][hl * 64 + 2 * lane];
        o0 += pj * vv.x;
        o1 += pj * vv.y;
    }
#pragma unroll
    for (int j = 0; j < 9; j++) {
        float pj = __shfl_sync(0xFFFFFFFFu, prob, j);
        int rj = __shfl_sync(0xFFFFFFFFu, row, j);
        float2 vv = *(const float2*)(vb + (size_t)rj * DM + hdim + 2 * lane);
        o0 += pj * vv.x;
        o1 += pj * vv.y;
    }

    const int xa = (p >> 1) & 3;
    const int d0 = 2 * lane;
    const int k0 = d0 & 15;
    const int base = d0 & ~15;
    const int pos0 = (((k0 & 3) ^ xa) << 2) | (k0 >> 2);
    const int pos1 = ((((k0 + 1) & 3) ^ xa) << 2) | ((k0 + 1) >> 2);
    float* ob = obp + (size_t)p * DM + hdim + base;
    ob[pos0] = rndf(o0);
    ob[pos1] = rndf(o1);
}

// ---------------------------------------------------------------------------
// Global attention merge (writes permuted+rounded).
// ---------------------------------------------------------------------------
__global__ __launch_bounds__(64)
void global_attn_merge_kernel(float* __restrict__ obp) {
    const int ph = blockIdx.x;
    const int h = ph & (NH - 1);
    const int p = (ph >> 4) ? (SEQ - 1) : 0;
    const int t = threadIdx.x;

    float M = -1e30f;
#pragma unroll
    for (int i = 0; i < GCH; i++) M = fmaxf(M, g_pm[ph][i]);
    float S = 0.f, O = 0.f;
#pragma unroll
    for (int i = 0; i < GCH; i++) {
        float w = __expf(g_pm[ph][i] - M);
        S += w * g_ps[ph][i];
        O += w * g_po[ph][i][t];
    }
    const int xa = (p >> 1) & 3;
    const int kk = t & 15;
    const int pos = (((kk & 3) ^ xa) << 2) | (kk >> 2);
    obp[(size_t)p * DM + h * HD + (t & ~15) + pos] = rndf(O / S);
}

// ---------------------------------------------------------------------------
// Launch. ncu profiles the 4th launch -> fused sparse_global_kernel.
// ---------------------------------------------------------------------------
extern "C" void kernel_launch(void* const* d_in, const int* in_sizes, int n_in,
                              void* d_out, int out_size) {
    const float* Q  = (const float*)d_in[0];
    const float* K  = (const float*)d_in[1];
    const float* V  = (const float*)d_in[2];
    const float* Wq = (const float*)d_in[3];
    const float* Wk = (const float*)d_in[4];
    const float* Wv = (const float*)d_in[5];
    const float* Wo = (const float*)d_in[6];
    const void*  idx = d_in[7];
    float* out = (float*)d_out;

    float *q, *k, *v, *qp, *kp, *vp, *attnp, *wqp, *wkp, *wvp, *wop;
    cudaGetSymbolAddress((void**)&q,     g_q);
    cudaGetSymbolAddress((void**)&k,     g_k);
    cudaGetSymbolAddress((void**)&v,     g_v);
    cudaGetSymbolAddress((void**)&qp,    g_qp);
    cudaGetSymbolAddress((void**)&kp,    g_kp);
    cudaGetSymbolAddress((void**)&vp,    g_vp);
    cudaGetSymbolAddress((void**)&attnp, g_attnp);
    cudaGetSymbolAddress((void**)&wqp,   g_wqp);
    cudaGetSymbolAddress((void**)&wkp,   g_wkp);
    cudaGetSymbolAddress((void**)&wvp,   g_wvp);
    cudaGetSymbolAddress((void**)&wop,   g_wop);

    cudaFuncSetAttribute(gemm_v8_kernel, cudaFuncAttributeMaxDynamicSharedMemorySize, GEMM_SMEM);
    // Round-16 lever: request the full 228KB shared carveout so 4 CTAs/SM fit
    // (default carveout capped residency at 2 CTAs -> occ 46%).
    cudaFuncSetAttribute(sparse_global_kernel,
                         cudaFuncAttributePreferredSharedMemoryCarveout, 100);

    detect_idx_kernel<<<1, 1>>>((const int*)idx);                              // 1

    dim3 gp(1024, 1, 7);
    perm_all_kernel<<<gp, 256>>>(Q, qp, K, kp, V, vp,
                                 Wq, wqp, Wk, wkp, Wv, wvp, Wo, wop);          // 2

    dim3 gg(8, 32, 3);
    gemm_v8_kernel<<<gg, 256, GEMM_SMEM>>>(qp, wqp, q, kp, wkp, k, vp, wvp, v); // 3

    dim3 gsp(512 + 32, 8);   // x<512: sparse, x>=512: global partials
    sparse_global_kernel<<<gsp, 512>>>(q, k, v, idx, attnp);                   // 4 (profiled)

    global_attn_merge_kernel<<<32, 64>>>(attnp);                               // 5

    dim3 go(8, 32, 1);
    gemm_v8_kernel<<<go, 256, GEMM_SMEM>>>(attnp, wop, out,
                                           attnp, wop, out, attnp, wop, out);  // 6
}

// round 17
// speedup vs baseline: 1.0335x; 1.0335x over previous
#include <cuda_runtime.h>
#include <cstdint>
#include <cstddef>

#define SEQ 4096
#define DM  1024
#define NH  16
#define HD  64
#define NKEY 32
#define NNG 4094

// Scratch (device globals: allocation-free)
__device__ float g_q[SEQ * DM];
__device__ float g_k[SEQ * DM];
__device__ float g_v[SEQ * DM];
__device__ float g_qp[SEQ * DM];      // permuted+rounded A operands
__device__ float g_kp[SEQ * DM];
__device__ float g_vp[SEQ * DM];
__device__ float g_attnp[SEQ * DM];   // attention out, permuted+rounded
__device__ float g_wqp[DM * DM];      // permuted+rounded weights [kt][n][16]
__device__ float g_wkp[DM * DM];
__device__ float g_wvp[DM * DM];
__device__ float g_wop[DM * DM];
__device__ int   g_idx_is64;

#define GCH 32
__device__ float g_pm[32][GCH];
__device__ float g_ps[32][GCH];
__device__ float g_po[32][GCH][HD];

// ---------------------------------------------------------------------------
__global__ void detect_idx_kernel(const int* __restrict__ idx32) {
    g_idx_is64 = ((idx32[1] | idx32[3] | idx32[5] | idx32[7]) == 0) ? 1 : 0;
}

// ---------------------------------------------------------------------------
// Helpers
// ---------------------------------------------------------------------------
__device__ __forceinline__ uint32_t f2tf32(float x) {
    uint32_t r;
    asm("cvt.rna.tf32.f32 %0, %1;" : "=r"(r) : "f"(x));
    return r;
}
__device__ __forceinline__ float rndf(float x) { return __uint_as_float(f2tf32(x)); }

__device__ __forceinline__ uint32_t smem_u32(const void* p) {
    uint32_t a;
    asm("{ .reg .u64 t; cvta.to.shared.u64 t, %1; cvt.u32.u64 %0, t; }" : "=r"(a) : "l"(p));
    return a;
}
__device__ __forceinline__ void cp16(uint32_t dst, const void* src) {
    asm volatile("cp.async.cg.shared.global [%0], [%1], 16;" :: "r"(dst), "l"(src));
}
__device__ __forceinline__ void mma_tf32(float c[4], const uint32_t a[4], const uint32_t b[2]) {
    asm volatile(
        "mma.sync.aligned.m16n8k8.row.col.f32.tf32.tf32.f32 "
        "{%0,%1,%2,%3}, {%4,%5,%6,%7}, {%8,%9}, {%0,%1,%2,%3};"
        : "+f"(c[0]), "+f"(c[1]), "+f"(c[2]), "+f"(c[3])
        : "r"(a[0]), "r"(a[1]), "r"(a[2]), "r"(a[3]),
          "r"(b[0]), "r"(b[1]));
}
#define NBAR(id, cnt) asm volatile("bar.sync %0, %1;" :: "r"(id), "r"(cnt) : "memory")

// ---------------------------------------------------------------------------
// Fused permute+round (z=0..2: A operands; z=3..6: weights).
// ---------------------------------------------------------------------------
__global__ __launch_bounds__(256)
void perm_all_kernel(const float* __restrict__ s0, float* __restrict__ d0,
                     const float* __restrict__ s1, float* __restrict__ d1,
                     const float* __restrict__ s2, float* __restrict__ d2,
                     const float* __restrict__ w0, float* __restrict__ p0,
                     const float* __restrict__ w1, float* __restrict__ p1,
                     const float* __restrict__ w2, float* __restrict__ p2,
                     const float* __restrict__ w3, float* __restrict__ p3) {
    const int z = blockIdx.z;
    if (z < 3) {
        const float* src = (z == 0) ? s0 : (z == 1) ? s1 : s2;
        float*       dst = (z == 0) ? d0 : (z == 1) ? d1 : d2;
        const int idx = blockIdx.x * 256 + threadIdx.x;
        const int row = idx >> 6, ch = idx & 63;
        const float4* s = (const float4*)(src + (size_t)row * DM + ch * 16);
        float4 u0 = s[0], u1 = s[1], u2 = s[2], u3 = s[3];
        float vv[16] = { u0.x,u0.y,u0.z,u0.w, u1.x,u1.y,u1.z,u1.w,
                         u2.x,u2.y,u2.z,u2.w, u3.x,u3.y,u3.z,u3.w };
        const int xa = (row >> 1) & 3;
        float4* d = (float4*)(dst + (size_t)row * DM + ch * 16);
#pragma unroll
        for (int x = 0; x < 4; x++) {
            const int kq = x ^ xa;
            float4 o;
            o.x = rndf(vv[kq]); o.y = rndf(vv[kq + 4]);
            o.z = rndf(vv[kq + 8]); o.w = rndf(vv[kq + 12]);
            d[x] = o;
        }
    } else {
        if (blockIdx.x >= 256) return;
        const int zi = z - 3;
        const float* W = (zi == 0) ? w0 : (zi == 1) ? w1 : (zi == 2) ? w2 : w3;
        float*       P = (zi == 0) ? p0 : (zi == 1) ? p1 : (zi == 2) ? p2 : p3;
        const int idx = blockIdx.x * 256 + threadIdx.x;
        const int kt = idx >> 10, n = idx & 1023;
        float out[16];
#pragma unroll
        for (int k = 0; k < 16; k++)
            out[((k & 3) << 2) + (k >> 2)] = rndf(W[(size_t)(kt * 16 + k) * DM + n]);
        float4* d = (float4*)(P + (size_t)kt * (DM * 16) + (size_t)n * 16);
#pragma unroll
        for (int x = 0; x < 4; x++)
            d[x] = make_float4(out[4 * x], out[4 * x + 1], out[4 * x + 2], out[4 * x + 3]);
    }
}

// ---------------------------------------------------------------------------
// GEMM v8 (round-15 version, unchanged).
// ---------------------------------------------------------------------------
#define STG 16384
#define GEMM_SMEM (4 * STG)

__global__ void __launch_bounds__(256, 2)
gemm_v8_kernel(const float* __restrict__ A0, const float* __restrict__ W0, float* __restrict__ C0,
               const float* __restrict__ A1, const float* __restrict__ W1, float* __restrict__ C1,
               const float* __restrict__ A2, const float* __restrict__ W2, float* __restrict__ C2) {
    extern __shared__ char sm[];
    const float* Ap = (blockIdx.z == 0) ? A0 : (blockIdx.z == 1) ? A1 : A2;
    const float* Wp = (blockIdx.z == 0) ? W0 : (blockIdx.z == 1) ? W1 : W2;
    float*       C  = (blockIdx.z == 0) ? C0 : (blockIdx.z == 1) ? C1 : C2;

    const uint32_t sb = smem_u32(sm);
    const int t = threadIdx.x, lane = t & 31, warp = t >> 5;
    const int wr = warp >> 2, wc = warp & 3;
    const int bm = blockIdx.y * 128, bn = blockIdx.x * 128;

    const float* qA0 = Ap + (size_t)(bm + (t >> 2)) * DM + (t & 3) * 4;
    const float* qA1 = qA0 + (size_t)64 * DM;
    const float* qB0 = Wp + (size_t)bn * 16 + t * 4;
    const float* qB1 = qB0 + 1024;
    const uint32_t dA0 = sb + t * 16, dA1 = sb + (t + 256) * 16;
    const uint32_t dB0 = sb + 8192 + t * 16, dB1 = sb + 8192 + (t + 256) * 16;

    const int g = lane & 3;
    int offA0[4], offA1[4], offB[4];
    {
        const int c0 = wc * 32 + (lane >> 2);
#pragma unroll
        for (int ni = 0; ni < 4; ni++) offB[ni] = (c0 + ni * 8) * 4 + g;
#pragma unroll
        for (int mi = 0; mi < 4; mi++) {
            const int rlo = wr * 64 + mi * 16 + (lane >> 2);
            const int rhi = rlo + 8;
            offA0[mi] = rlo * 4 + ((g ^ (rlo >> 1)) & 3);
            offA1[mi] = rhi * 4 + ((g ^ (rhi >> 1)) & 3);
        }
    }

    float acc[4][4][4];
#pragma unroll
    for (int mi = 0; mi < 4; mi++)
#pragma unroll
        for (int ni = 0; ni < 4; ni++)
#pragma unroll
            for (int e = 0; e < 4; e++) acc[mi][ni][e] = 0.f;

#pragma unroll
    for (int pt = 0; pt < 3; pt++) {
        cp16(dA0 + pt * STG, qA0 + pt * 16);
        cp16(dA1 + pt * STG, qA1 + pt * 16);
        cp16(dB0 + pt * STG, qB0 + (size_t)pt * DM * 16);
        cp16(dB1 + pt * STG, qB1 + (size_t)pt * DM * 16);
        asm volatile("cp.async.commit_group;" ::: "memory");
    }
    const float* rA0 = qA0 + 48;
    const float* rA1 = qA1 + 48;
    const float* rB0 = qB0 + (size_t)3 * DM * 16;
    const float* rB1 = qB1 + (size_t)3 * DM * 16;

    const int NT = 64;
#pragma unroll 4
    for (int kt = 0; kt < NT; kt++) {
        asm volatile("cp.async.wait_group 2;" ::: "memory");
        __syncthreads();

        const uint32_t s = kt & 3;
        const float4* as4 = (const float4*)(sm + s * STG);
        const float4* bs4 = (const float4*)(sm + s * STG + 8192);

        float4 bq[4];
#pragma unroll
        for (int ni = 0; ni < 4; ni++) bq[ni] = bs4[offB[ni]];

#pragma unroll
        for (int half = 0; half < 2; half++) {
            float4 alo[2], ahi[2];
#pragma unroll
            for (int u = 0; u < 2; u++) {
                const int mi = half * 2 + u;
                alo[u] = as4[offA0[mi]];
                ahi[u] = as4[offA1[mi]];
            }
#pragma unroll
            for (int u = 0; u < 2; u++) {
                const int mi = half * 2 + u;
                uint32_t a0[4] = { __float_as_uint(alo[u].x), __float_as_uint(ahi[u].x),
                                   __float_as_uint(alo[u].y), __float_as_uint(ahi[u].y) };
#pragma unroll
                for (int ni = 0; ni < 4; ni++) {
                    uint32_t b0[2] = { __float_as_uint(bq[ni].x), __float_as_uint(bq[ni].y) };
                    mma_tf32(acc[mi][ni], a0, b0);
                }
            }
#pragma unroll
            for (int u = 0; u < 2; u++) {
                const int mi = half * 2 + u;
                uint32_t a1[4] = { __float_as_uint(alo[u].z), __float_as_uint(ahi[u].z),
                                   __float_as_uint(alo[u].w), __float_as_uint(ahi[u].w) };
#pragma unroll
                for (int ni = 0; ni < 4; ni++) {
                    uint32_t b1[2] = { __float_as_uint(bq[ni].z), __float_as_uint(bq[ni].w) };
                    mma_tf32(acc[mi][ni], a1, b1);
                }
            }
        }

        if (kt + 3 < NT) {
            const uint32_t ns = (kt + 3) & 3;
            cp16(dA0 + ns * STG, rA0);
            cp16(dA1 + ns * STG, rA1);
            cp16(dB0 + ns * STG, rB0);
            cp16(dB1 + ns * STG, rB1);
        }
        asm volatile("cp.async.commit_group;" ::: "memory");
        rA0 += 16; rA1 += 16;
        rB0 += (size_t)DM * 16; rB1 += (size_t)DM * 16;
    }

#pragma unroll
    for (int mi = 0; mi < 4; mi++) {
#pragma unroll
        for (int ni = 0; ni < 4; ni++) {
            const int r = bm + wr * 64 + mi * 16 + (lane >> 2);
            const int c = bn + wc * 32 + ni * 8 + ((lane & 3) << 1);
            float2 v0 = make_float2(acc[mi][ni][0], acc[mi][ni][1]);
            float2 v1 = make_float2(acc[mi][ni][2], acc[mi][ni][3]);
            *(float2*)(C + (size_t)r * DM + c) = v0;
            *(float2*)(C + (size_t)(r + 8) * DM + c) = v1;
        }
    }
}

// ---------------------------------------------------------------------------
// Fused sparse + global attention v3: 256 threads, 1 head per block.
// smem 18.4KB/block -> 5 CTAs/SM (was 41KB -> 2 CTAs, occ 46%).
// x < 512 : sparse, 8 warps = 8 queries x 1 head (head = blockIdx.y).
// x >= 512: global partials, 2 x 128-thread subunits per block.
// All shared state in one aliased buffer (paths are block-disjoint).
// ---------------------------------------------------------------------------
#define TQ 8
#define WROWS 30
#define WP 68     // row stride floats: 17 x 16B units, 17 mod 8 = 1 (conflict-free)

// sQ: 8*64 = 512 floats; sK: 30*68 = 2040; sV: 2040  -> total 4592 floats
#define SB_TOTAL (512 + 2040 + 2040)

__global__ __launch_bounds__(256)
void sparse_global_kernel(const float* __restrict__ qb, const float* __restrict__ kb,
                          const float* __restrict__ vb, const void* __restrict__ idxp,
                          float* __restrict__ obp) {
    __shared__ float sbuf[SB_TOTAL];
    const int t = threadIdx.x;

    if (blockIdx.x >= 512) {
        // ------------------- global attention partials -------------------
        const int sub = t >> 7;          // 0..1
        const int tt = t & 127;
        const int unit = ((blockIdx.x - 512) * 16 + blockIdx.y) * 2 + sub;  // 0..1023
        const int c = unit & (GCH - 1);
        const int ph = unit >> 5;
        const int h = ph & (NH - 1);
        const int p = (ph >> 4) ? (SEQ - 1) : 0;
        const int j0 = c * 128;
        const int bid = sub + 1;

        float* gq   = sbuf + sub * 320;        // 64
        float* gle  = gq + 64;                 // 128
        float* gred = gle + 128;               // 128

        if (tt < HD / 4)
            ((float4*)gq)[tt] = *(const float4*)(qb + (size_t)p * DM + h * HD + tt * 4);
        NBAR(bid, 128);

        const float* kr = kb + (size_t)(j0 + tt) * DM + h * HD;
        float a = 0.f;
#pragma unroll
        for (int cc = 0; cc < 16; cc++) {
            float4 kv = ((const float4*)kr)[cc];
            float4 qv = ((const float4*)gq)[cc];
            a += kv.x * qv.x + kv.y * qv.y + kv.z * qv.z + kv.w * qv.w;
        }
        float logit = a * 0.125f;

        gred[tt] = logit; NBAR(bid, 128);
#pragma unroll
        for (int o = 64; o > 0; o >>= 1) {
            if (tt < o) gred[tt] = fmaxf(gred[tt], gred[tt + o]);
            NBAR(bid, 128);
        }
        const float m = gred[0];
        NBAR(bid, 128);

        float e = __expf(logit - m);
        gle[tt] = e;
        gred[tt] = e; NBAR(bid, 128);
#pragma unroll
        for (int o = 64; o > 0; o >>= 1) {
            if (tt < o) gred[tt] += gred[tt + o];
            NBAR(bid, 128);
        }
        const float s = gred[0];
        NBAR(bid, 128);

        const int d = tt & (HD - 1);
        const int hh = tt >> 6;
        float o = 0.f;
#pragma unroll 4
        for (int j = hh * 64; j < hh * 64 + 64; j++)
            o += gle[j] * vb[(size_t)(j0 + j) * DM + h * HD + d];
        gred[tt] = o; NBAR(bid, 128);
        if (tt < HD)
            g_po[ph][c][tt] = gred[tt] + gred[tt + 64];
        if (tt == 0) { g_pm[ph][c] = m; g_ps[ph][c] = s; }
        return;
    }

    // ----------------------------- sparse path -----------------------------
    float* sQ = sbuf;                    // [8][64]
    float* sK = sbuf + 512;              // [30][WP]
    float* sV = sbuf + 512 + WROWS * WP; // [30][WP]

    const int pbase = blockIdx.x * TQ + 1;
    const int h = blockIdx.y;
    const int hd0 = h * HD;
    const int r0 = pbase - 11;

    // stage Q: 8 rows x 16 float4
    if (t < 128) {
        int row = t >> 4, i = (t & 15) << 2;
        int p = pbase + row;
        if (p <= SEQ - 2)
            *(float4*)&sQ[row * 64 + i] = *(const float4*)(qb + (size_t)p * DM + hd0 + i);
    }
    // stage K/V window union: 2 x 30 rows x 16 float4 = 960 chunks
#pragma unroll
    for (int f = t; f < 2 * WROWS * 16; f += 256) {
        int sel = (f >= WROWS * 16);
        int rem = sel ? f - WROWS * 16 : f;
        int row = rem >> 4, i = (rem & 15) << 2;
        int rg = r0 + row;
        rg = rg < 0 ? 0 : (rg > SEQ - 1 ? SEQ - 1 : rg);
        const float* src = (sel ? vb : kb) + (size_t)rg * DM + hd0 + i;
        float* dst = (sel ? sV : sK) + row * WP + i;
        *(float4*)dst = *(const float4*)src;
    }
    __syncthreads();

    const int warp = t >> 5, lane = t & 31;
    const int ql = warp;
    const int p = pbase + ql;
    if (p > SEQ - 2) return;
    const int n = p - 1;

    const float4* qp4 = (const float4*)&sQ[ql * 64];

    int row = 0;
    float logit;
    if (lane >= 9) {
        const float4* kp4 = (const float4*)&sK[(ql + lane - 9) * WP];
        float a = 0.f;
#pragma unroll
        for (int c = 0; c < 16; c++) {
            float4 kv = kp4[c];
            float4 qv = qp4[c];
            a += kv.x * qv.x + kv.y * qv.y + kv.z * qv.z + kv.w * qv.w;
        }
        logit = a * 0.125f;
    } else {
        if (lane >= 1) {
            row = g_idx_is64
                ? (int)((const long long*)idxp)[(size_t)n * NKEY + lane]
                : ((const int*)idxp)[(size_t)n * NKEY + lane];
        }
        const float4* kp4 = (const float4*)(kb + (size_t)row * DM + hd0);
        float a = 0.f;
#pragma unroll
        for (int c = 0; c < 16; c++) {
            float4 kv = kp4[c];
            float4 qv = qp4[c];
            a += kv.x * qv.x + kv.y * qv.y + kv.z * qv.z + kv.w * qv.w;
        }
        logit = a * 0.125f;
    }

    float m = logit;
#pragma unroll
    for (int o = 16; o > 0; o >>= 1) m = fmaxf(m, __shfl_xor_sync(0xFFFFFFFFu, m, o));
    float e = __expf(logit - m);
    float s = e;
#pragma unroll
    for (int o = 16; o > 0; o >>= 1) s += __shfl_xor_sync(0xFFFFFFFFu, s, o);
    const float prob = e / s;

    float o0 = 0.f, o1 = 0.f;
#pragma unroll
    for (int j = 9; j < 32; j++) {
        float pj = __shfl_sync(0xFFFFFFFFu, prob, j);
        float2 vv = *(const float2*)&sV[(ql + j - 9) * WP + 2 * lane];
        o0 += pj * vv.x;
        o1 += pj * vv.y;
    }
#pragma unroll
    for (int j = 0; j < 9; j++) {
        float pj = __shfl_sync(0xFFFFFFFFu, prob, j);
        int rj = __shfl_sync(0xFFFFFFFFu, row, j);
        float2 vv = *(const float2*)(vb + (size_t)rj * DM + hd0 + 2 * lane);
        o0 += pj * vv.x;
        o1 += pj * vv.y;
    }

    const int xa = (p >> 1) & 3;
    const int d0 = 2 * lane;
    const int k0 = d0 & 15;
    const int base = d0 & ~15;
    const int pos0 = (((k0 & 3) ^ xa) << 2) | (k0 >> 2);
    const int pos1 = ((((k0 + 1) & 3) ^ xa) << 2) | ((k0 + 1) >> 2);
    float* ob = obp + (size_t)p * DM + hd0 + base;
    ob[pos0] = rndf(o0);
    ob[pos1] = rndf(o1);
}

// ---------------------------------------------------------------------------
// Global attention merge (writes permuted+rounded).
// ---------------------------------------------------------------------------
__global__ __launch_bounds__(64)
void global_attn_merge_kernel(float* __restrict__ obp) {
    const int ph = blockIdx.x;
    const int h = ph & (NH - 1);
    const int p = (ph >> 4) ? (SEQ - 1) : 0;
    const int t = threadIdx.x;

    float M = -1e30f;
#pragma unroll
    for (int i = 0; i < GCH; i++) M = fmaxf(M, g_pm[ph][i]);
    float S = 0.f, O = 0.f;
#pragma unroll
    for (int i = 0; i < GCH; i++) {
        float w = __expf(g_pm[ph][i] - M);
        S += w * g_ps[ph][i];
        O += w * g_po[ph][i][t];
    }
    const int xa = (p >> 1) & 3;
    const int kk = t & 15;
    const int pos = (((kk & 3) ^ xa) << 2) | (kk >> 2);
    obp[(size_t)p * DM + h * HD + (t & ~15) + pos] = rndf(O / S);
}

// ---------------------------------------------------------------------------
// Launch. ncu profiles the 4th launch -> fused sparse_global_kernel.
// ---------------------------------------------------------------------------
extern "C" void kernel_launch(void* const* d_in, const int* in_sizes, int n_in,
                              void* d_out, int out_size) {
    const float* Q  = (const float*)d_in[0];
    const float* K  = (const float*)d_in[1];
    const float* V  = (const float*)d_in[2];
    const float* Wq = (const float*)d_in[3];
    const float* Wk = (const float*)d_in[4];
    const float* Wv = (const float*)d_in[5];
    const float* Wo = (const float*)d_in[6];
    const void*  idx = d_in[7];
    float* out = (float*)d_out;

    float *q, *k, *v, *qp, *kp, *vp, *attnp, *wqp, *wkp, *wvp, *wop;
    cudaGetSymbolAddress((void**)&q,     g_q);
    cudaGetSymbolAddress((void**)&k,     g_k);
    cudaGetSymbolAddress((void**)&v,     g_v);
    cudaGetSymbolAddress((void**)&qp,    g_qp);
    cudaGetSymbolAddress((void**)&kp,    g_kp);
    cudaGetSymbolAddress((void**)&vp,    g_vp);
    cudaGetSymbolAddress((void**)&attnp, g_attnp);
    cudaGetSymbolAddress((void**)&wqp,   g_wqp);
    cudaGetSymbolAddress((void**)&wkp,   g_wkp);
    cudaGetSymbolAddress((void**)&wvp,   g_wvp);
    cudaGetSymbolAddress((void**)&wop,   g_wop);

    cudaFuncSetAttribute(gemm_v8_kernel, cudaFuncAttributeMaxDynamicSharedMemorySize, GEMM_SMEM);

    detect_idx_kernel<<<1, 1>>>((const int*)idx);                              // 1

    dim3 gp(1024, 1, 7);
    perm_all_kernel<<<gp, 256>>>(Q, qp, K, kp, V, vp,
                                 Wq, wqp, Wk, wkp, Wv, wvp, Wo, wop);          // 2

    dim3 gg(8, 32, 3);
    gemm_v8_kernel<<<gg, 256, GEMM_SMEM>>>(qp, wqp, q, kp, wkp, k, vp, wvp, v); // 3

    dim3 gsp(512 + 32, 16);   // x<512: sparse (1 head per block), x>=512: global
    sparse_global_kernel<<<gsp, 256>>>(q, k, v, idx, attnp);                   // 4 (profiled)

    global_attn_merge_kernel<<<32, 64>>>(attnp);                               // 5

    dim3 go(8, 32, 1);
    gemm_v8_kernel<<<go, 256, GEMM_SMEM>>>(attnp, wop, out,
                                           attnp, wop, out, attnp, wop, out);  // 6
}